// round 14
// baseline (speedup 1.0000x reference)
#include <cuda_runtime.h>
#include <math.h>
#include <stdint.h>

#define SQ 200
#define BB 1024
#define DD 128
#define NL1 80
#define NL2 40
#define M_TOT (SQ*BB)   // 204800

typedef unsigned long long ull;

#define FFMA2(acc, a, b) asm("fma.rn.f32x2 %0, %1, %2, %0;" : "+l"(acc) : "l"(a), "l"(b))
#define DUPF2(dst, f)    asm("mov.b64 %0, {%1, %1};" : "=l"(dst) : "f"(f))
#define UNPK2(lo, hi, v) asm("mov.b64 {%0, %1}, %2;" : "=f"(lo), "=f"(hi) : "l"(v))

// scratch (allocation-free rule: __device__ globals)
__device__ float g_H1[M_TOT*NL1];
__device__ float g_H2[M_TOT*NL2];
__device__ float g_mean1[BB*NL1];
__device__ float g_istd1[BB*NL1];
__device__ int   g_mask_mode;   // 0=uint8, 1=int32, 2=float32

// ---------------------------------------------------------------------------
// K0: classify mask buffer dtype from its first 256 32-bit words.
// ---------------------------------------------------------------------------
__global__ void k0_detect_mask(const void* __restrict__ mask)
{
    const unsigned int* w = (const unsigned int*)mask;
    bool i32 = true, f32 = true;
    for (int i = threadIdx.x; i < 256; i += 32) {
        unsigned int v = w[i];
        if (v > 1u) i32 = false;
        if (v != 0u && v != 0x3F800000u) f32 = false;
    }
    i32 = __all_sync(0xffffffffu, i32);
    f32 = __all_sync(0xffffffffu, f32);
    if (threadIdx.x == 0) g_mask_mode = i32 ? 1 : (f32 ? 2 : 0);
}

// ---------------------------------------------------------------------------
// K1: per-query-row effective GEMM with packed f32x2 FMA.
// block b2: rows m in [b2*200, b2*200+200):
//   pre1[m,n] = qa[n] + sum_d facts[m,d]*wef[d,n]
// thread tile: 8 rows x 4 cols; row operand loads as packed f32x2 pairs.
// ---------------------------------------------------------------------------
__global__ __launch_bounds__(320) void k1_gemm1(
    const float* __restrict__ query, const float* __restrict__ facts,
    const float* __restrict__ W1, const float* __restrict__ b1v)
{
    extern __shared__ float sm[];
    float* q   = sm;                      // 128
    float* qa  = sm + 128;                // 80
    float* wef = sm + 208;                // 128*80
    float* fs  = sm + 208 + DD*NL1;       // 132*128 transposed facts chunk
    const int tid = threadIdx.x;
    const int b2  = blockIdx.x;

    if (tid < DD) q[tid] = query[b2*DD + tid];
    __syncthreads();

    for (int i = tid; i < DD*NL1; i += 320) {
        int d = i / NL1, n = i - d*NL1;
        wef[i] = W1[(DD+d)*NL1 + n] - W1[(3*DD+d)*NL1 + n] + q[d]*W1[(2*DD+d)*NL1 + n];
    }
    if (tid < NL1) {
        float s = b1v[tid];
        #pragma unroll 4
        for (int d = 0; d < DD; d++)
            s += q[d]*(W1[d*NL1 + tid] + W1[(3*DD+d)*NL1 + tid]);
        qa[tid] = s;
    }
    __syncthreads();

    const int tx   = tid & 7;          // 8 rows each
    const int half = (tid >> 3) & 1;   // +64 rows
    const int ty   = tid >> 4;         // 0..19, 4 cols each
    const int rowbase = half*64 + tx*8;
    const float4 qv = *reinterpret_cast<const float4*>(qa + (ty<<2));

    for (int mb = 0; mb < SQ; mb += 128) {
        const int rows = min(128, SQ - mb);
        const float* fp = facts + (size_t)(b2*SQ + mb)*DD;
        // load + transpose facts chunk (float4 loads, scalar transposed stores)
        for (int i = tid; i < 32*128; i += 320) {
            int r = i >> 5, d4 = (i & 31) << 2;
            float4 v = (r < rows) ? *reinterpret_cast<const float4*>(fp + (size_t)r*DD + d4)
                                  : make_float4(0.f,0.f,0.f,0.f);
            fs[(d4+0)*132 + r] = v.x;
            fs[(d4+1)*132 + r] = v.y;
            fs[(d4+2)*132 + r] = v.z;
            fs[(d4+3)*132 + r] = v.w;
        }
        __syncthreads();

        ull acc[4][4];
        #pragma unroll
        for (int p = 0; p < 4; p++)
            #pragma unroll
            for (int j = 0; j < 4; j++) acc[p][j] = 0ull;

        #pragma unroll 2
        for (int d = 0; d < DD; d++) {
            const ulonglong2 f01 = *reinterpret_cast<const ulonglong2*>(fs + d*132 + rowbase);
            const ulonglong2 f23 = *reinterpret_cast<const ulonglong2*>(fs + d*132 + rowbase + 4);
            const float4 wv = *reinterpret_cast<const float4*>(wef + d*NL1 + (ty<<2));
            ull wd0, wd1, wd2, wd3;
            DUPF2(wd0, wv.x); DUPF2(wd1, wv.y); DUPF2(wd2, wv.z); DUPF2(wd3, wv.w);
            FFMA2(acc[0][0], f01.x, wd0); FFMA2(acc[0][1], f01.x, wd1);
            FFMA2(acc[0][2], f01.x, wd2); FFMA2(acc[0][3], f01.x, wd3);
            FFMA2(acc[1][0], f01.y, wd0); FFMA2(acc[1][1], f01.y, wd1);
            FFMA2(acc[1][2], f01.y, wd2); FFMA2(acc[1][3], f01.y, wd3);
            FFMA2(acc[2][0], f23.x, wd0); FFMA2(acc[2][1], f23.x, wd1);
            FFMA2(acc[2][2], f23.x, wd2); FFMA2(acc[2][3], f23.x, wd3);
            FFMA2(acc[3][0], f23.y, wd0); FFMA2(acc[3][1], f23.y, wd1);
            FFMA2(acc[3][2], f23.y, wd2); FFMA2(acc[3][3], f23.y, wd3);
        }

        #pragma unroll
        for (int p = 0; p < 4; p++) {
            float lo0,hi0,lo1,hi1,lo2,hi2,lo3,hi3;
            UNPK2(lo0,hi0,acc[p][0]); UNPK2(lo1,hi1,acc[p][1]);
            UNPK2(lo2,hi2,acc[p][2]); UNPK2(lo3,hi3,acc[p][3]);
            int r0 = mb + rowbase + p*2;
            if (r0 < SQ) {
                float4 o = make_float4(lo0+qv.x, lo1+qv.y, lo2+qv.z, lo3+qv.w);
                *reinterpret_cast<float4*>(g_H1 + (size_t)(b2*SQ + r0)*NL1 + (ty<<2)) = o;
            }
            if (r0+1 < SQ) {
                float4 o = make_float4(hi0+qv.x, hi1+qv.y, hi2+qv.z, hi3+qv.w);
                *reinterpret_cast<float4*>(g_H1 + (size_t)(b2*SQ + r0+1)*NL1 + (ty<<2)) = o;
            }
        }
        __syncthreads();
    }
}

// ---------------------------------------------------------------------------
// K2: stats over S for layer 1, vectorized float4. element (s,b,l) at
// s*81920 + b*80 + l. thread handles 4 consecutive (b,l) keys.
// ---------------------------------------------------------------------------
__global__ void k2_stats1()
{
    int idx4 = blockIdx.x*blockDim.x + threadIdx.x;   // 0..20479
    if (idx4 >= (BB*NL1)/4) return;
    const float* base = g_H1 + idx4*4;
    float4 s1 = make_float4(0,0,0,0), s2 = make_float4(0,0,0,0);
    #pragma unroll 4
    for (int s = 0; s < SQ; s++) {
        float4 v = *reinterpret_cast<const float4*>(base + (size_t)s*BB*NL1);
        s1.x += v.x; s1.y += v.y; s1.z += v.z; s1.w += v.w;
        s2.x = fmaf(v.x,v.x,s2.x); s2.y = fmaf(v.y,v.y,s2.y);
        s2.z = fmaf(v.z,v.z,s2.z); s2.w = fmaf(v.w,v.w,s2.w);
    }
    const float inS = 1.0f/SQ, inV = 1.0f/(SQ-1);
    float4 mu = make_float4(s1.x*inS, s1.y*inS, s1.z*inS, s1.w*inS);
    float4 is;
    is.x = rsqrtf(fmaxf((s2.x - s1.x*mu.x)*inV, 1e-20f));
    is.y = rsqrtf(fmaxf((s2.y - s1.y*mu.y)*inV, 1e-20f));
    is.z = rsqrtf(fmaxf((s2.z - s1.z*mu.z)*inV, 1e-20f));
    is.w = rsqrtf(fmaxf((s2.w - s1.w*mu.w)*inV, 1e-20f));
    *reinterpret_cast<float4*>(g_mean1 + idx4*4) = mu;
    *reinterpret_cast<float4*>(g_istd1 + idx4*4) = is;
}

// ---------------------------------------------------------------------------
// K3: dice(H1) @ W2 + b2 -> H2. 128 rows/block. tanh.approx sigmoid,
// packed f32x2 GEMM (thread tile 4 rows x 4 cols).
// ---------------------------------------------------------------------------
__global__ __launch_bounds__(320) void k3_dice_gemm2(
    const float* __restrict__ W2, const float* __restrict__ b2v,
    const float* __restrict__ a1p)
{
    extern __shared__ float sm[];
    float* hs  = sm;               // 80 * 132
    float* w2s = sm + NL1*132;     // 80*40
    float* bs  = w2s + NL1*NL2;    // 40
    const int tid = threadIdx.x;
    const int m0  = blockIdx.x * 128;
    const float alpha = a1p[0];
    const float c0 = 0.5f*(1.0f + alpha);
    const float c1 = 0.5f*(1.0f - alpha);

    for (int i = tid; i < NL1*NL2; i += 320) w2s[i] = W2[i];
    if (tid < NL2) bs[tid] = b2v[tid];

    for (int i = tid; i < 128*NL1; i += 320) {
        int r = i / NL1, l = i - r*NL1;
        int m = m0 + r;
        float v = g_H1[(size_t)m0*NL1 + i];
        int b = m & (BB-1);
        float z = (v - g_mean1[b*NL1 + l]) * g_istd1[b*NL1 + l];
        float t;
        asm("tanh.approx.f32 %0, %1;" : "=f"(t) : "f"(0.5f*z));
        hs[l*132 + r] = v * fmaf(c1, t, c0);
    }
    __syncthreads();

    const int tx = tid & 31;   // 4 rows each -> 128
    const int ty = tid >> 5;   // 0..9, 4 cols each -> 40
    ull acc[2][4];
    #pragma unroll
    for (int p = 0; p < 2; p++)
        #pragma unroll
        for (int j = 0; j < 4; j++) acc[p][j] = 0ull;

    #pragma unroll 4
    for (int k = 0; k < NL1; k++) {
        const ulonglong2 fpr = *reinterpret_cast<const ulonglong2*>(hs + k*132 + (tx<<2));
        const float4 wv = *reinterpret_cast<const float4*>(w2s + k*NL2 + (ty<<2));
        ull wd0, wd1, wd2, wd3;
        DUPF2(wd0, wv.x); DUPF2(wd1, wv.y); DUPF2(wd2, wv.z); DUPF2(wd3, wv.w);
        FFMA2(acc[0][0], fpr.x, wd0); FFMA2(acc[0][1], fpr.x, wd1);
        FFMA2(acc[0][2], fpr.x, wd2); FFMA2(acc[0][3], fpr.x, wd3);
        FFMA2(acc[1][0], fpr.y, wd0); FFMA2(acc[1][1], fpr.y, wd1);
        FFMA2(acc[1][2], fpr.y, wd2); FFMA2(acc[1][3], fpr.y, wd3);
    }

    const float4 bv = *reinterpret_cast<const float4*>(bs + (ty<<2));
    #pragma unroll
    for (int p = 0; p < 2; p++) {
        float lo0,hi0,lo1,hi1,lo2,hi2,lo3,hi3;
        UNPK2(lo0,hi0,acc[p][0]); UNPK2(lo1,hi1,acc[p][1]);
        UNPK2(lo2,hi2,acc[p][2]); UNPK2(lo3,hi3,acc[p][3]);
        int m = m0 + (tx<<2) + p*2;
        float4 o0 = make_float4(lo0+bv.x, lo1+bv.y, lo2+bv.z, lo3+bv.w);
        float4 o1 = make_float4(hi0+bv.x, hi1+bv.y, hi2+bv.z, hi3+bv.w);
        *reinterpret_cast<float4*>(g_H2 + (size_t)m*NL2 + (ty<<2)) = o0;
        *reinterpret_cast<float4*>(g_H2 + (size_t)(m+1)*NL2 + (ty<<2)) = o1;
    }
}

// ---------------------------------------------------------------------------
// K456: per-batch-column fused stats2 + dice2 + W3 dot + masked softmax +
// output scaling. One block per b.
// ---------------------------------------------------------------------------
__global__ __launch_bounds__(256) void k456_fused(
    const void* __restrict__ mask, const float* __restrict__ facts,
    const float* __restrict__ W3, const float* __restrict__ b3,
    const float* __restrict__ a2p, float* __restrict__ out)
{
    __shared__ float hcol[SQ*NL2];   // 200*40
    __shared__ float mstat[NL2], istat[NL2], w3s[NL2];
    __shared__ float wgt[SQ];
    __shared__ float red[8];
    const int b = blockIdx.x, tid = threadIdx.x;
    const int lane = tid & 31, wrp = tid >> 5;
    const float MASK_FILL = -4294967295.0f;
    const int mode = g_mask_mode;
    const float alpha = a2p[0];

    if (tid < NL2) w3s[tid] = W3[tid];

    // load H2 column (float4)
    for (int i4 = tid; i4 < SQ*NL2/4; i4 += 256) {
        int s = i4 / 10, l4 = (i4 - s*10) << 2;
        *reinterpret_cast<float4*>(hcol + s*NL2 + l4) =
            *reinterpret_cast<const float4*>(g_H2 + (size_t)s*BB*NL2 + b*NL2 + l4);
    }
    __syncthreads();

    // stats over s: warp wrp owns l in [wrp*5, wrp*5+5)
    #pragma unroll
    for (int k = 0; k < 5; k++) {
        int l = wrp*5 + k;
        float s1 = 0.f, s2 = 0.f;
        for (int s = lane; s < SQ; s += 32) {
            float v = hcol[s*NL2 + l];
            s1 += v; s2 = fmaf(v, v, s2);
        }
        #pragma unroll
        for (int o = 16; o; o >>= 1) {
            s1 += __shfl_xor_sync(0xffffffffu, s1, o);
            s2 += __shfl_xor_sync(0xffffffffu, s2, o);
        }
        if (lane == 0) {
            float mu = s1 * (1.0f/SQ);
            mstat[l] = mu;
            istat[l] = rsqrtf(fmaxf((s2 - s1*mu)*(1.0f/(SQ-1)), 1e-20f));
        }
    }
    __syncthreads();

    // logits (exact expf sigmoid, layer 2)
    float my = -3.4028235e38f;
    if (tid < SQ) {
        float acc = 0.f;
        #pragma unroll
        for (int l = 0; l < NL2; l++) {
            float v = hcol[tid*NL2 + l];
            float z = (v - mstat[l]) * istat[l];
            float p = 1.0f/(1.0f + __expf(-z));
            acc = fmaf(v * (alpha + (1.0f-alpha)*p), w3s[l], acc);
        }
        float lg = acc + b3[0];
        int idx = tid*BB + b;
        bool mv;
        if (mode == 1)      mv = ((const int*)mask)[idx] != 0;
        else if (mode == 2) mv = ((const float*)mask)[idx] != 0.0f;
        else                mv = ((const unsigned char*)mask)[idx] != 0;
        my = mv ? lg : MASK_FILL;
    }
    // block max
    float v = my;
    #pragma unroll
    for (int o = 16; o; o >>= 1) v = fmaxf(v, __shfl_xor_sync(0xffffffffu, v, o));
    if (lane == 0) red[wrp] = v;
    __syncthreads();
    float mx = red[0];
    #pragma unroll
    for (int i = 1; i < 8; i++) mx = fmaxf(mx, red[i]);
    __syncthreads();

    float e = (tid < SQ) ? __expf(my - mx) : 0.0f;
    float sv = e;
    #pragma unroll
    for (int o = 16; o; o >>= 1) sv += __shfl_xor_sync(0xffffffffu, sv, o);
    if (lane == 0) red[wrp] = sv;
    __syncthreads();
    float tot = 0.0f;
    #pragma unroll
    for (int i = 0; i < 8; i++) tot += red[i];
    if (tid < SQ) wgt[tid] = e / tot;
    __syncthreads();

    // out = wgt[s] * facts, float4
    const float* fb = facts + b*DD;
    float*       ob = out   + b*DD;
    for (int i = tid; i < SQ*(DD/4); i += 256) {
        int s = i >> 5, d4 = (i & 31) << 2;
        size_t off = (size_t)s*BB*DD + d4;
        float4 fv = *reinterpret_cast<const float4*>(fb + off);
        float w = wgt[s];
        float4 o = make_float4(w*fv.x, w*fv.y, w*fv.z, w*fv.w);
        *reinterpret_cast<float4*>(ob + off) = o;
    }
}

// ---------------------------------------------------------------------------
extern "C" void kernel_launch(void* const* d_in, const int* in_sizes, int n_in,
                              void* d_out, int out_size)
{
    const float* query = (const float*)d_in[0];
    const float* facts = (const float*)d_in[1];
    const void*  mask  = d_in[2];
    const float* W1 = (const float*)d_in[3];
    const float* b1 = (const float*)d_in[4];
    const float* a1 = (const float*)d_in[5];
    const float* W2 = (const float*)d_in[6];
    const float* b2 = (const float*)d_in[7];
    const float* a2 = (const float*)d_in[8];
    const float* W3 = (const float*)d_in[9];
    const float* b3 = (const float*)d_in[10];
    float* out = (float*)d_out;

    const size_t sm1 = (size_t)(128 + NL1 + DD*NL1 + 132*128) * sizeof(float);  // ~109.4 KB
    const size_t sm3 = (size_t)(NL1*132 + NL1*NL2 + NL2) * sizeof(float);       // ~55.2 KB
    cudaFuncSetAttribute(k1_gemm1,      cudaFuncAttributeMaxDynamicSharedMemorySize, (int)sm1);
    cudaFuncSetAttribute(k3_dice_gemm2, cudaFuncAttributeMaxDynamicSharedMemorySize, (int)sm3);

    k0_detect_mask<<<1, 32>>>(mask);
    k1_gemm1<<<BB, 320, sm1>>>(query, facts, W1, b1);
    k2_stats1<<<80, 256>>>();
    k3_dice_gemm2<<<M_TOT/128, 320, sm3>>>(W2, b2, a1);
    k456_fused<<<BB, 256>>>(mask, facts, W3, b3, a2, out);
}

// round 15
// speedup vs baseline: 1.0622x; 1.0622x over previous
#include <cuda_runtime.h>
#include <math.h>
#include <stdint.h>

#define SQ 200
#define BB 1024
#define DD 128
#define NL1 80
#define NL2 40
#define M_TOT (SQ*BB)   // 204800

typedef unsigned long long ull;

#define FFMA2(acc, a, b) asm("fma.rn.f32x2 %0, %1, %2, %0;" : "+l"(acc) : "l"(a), "l"(b))
#define DUPF2(dst, f)    asm("mov.b64 %0, {%1, %1};" : "=l"(dst) : "f"(f))
#define UNPK2(lo, hi, v) asm("mov.b64 {%0, %1}, %2;" : "=f"(lo), "=f"(hi) : "l"(v))

// scratch (allocation-free rule: __device__ globals)
__device__ float g_H1[M_TOT*NL1];
__device__ float g_H2[M_TOT*NL2];
__device__ float g_mean1[BB*NL1];
__device__ float g_istd1[BB*NL1];
__device__ int   g_mask_mode;   // 0=uint8, 1=int32, 2=float32

// ---------------------------------------------------------------------------
// K0: classify mask buffer dtype from its first 256 32-bit words.
// ---------------------------------------------------------------------------
__global__ void k0_detect_mask(const void* __restrict__ mask)
{
    const unsigned int* w = (const unsigned int*)mask;
    bool i32 = true, f32 = true;
    for (int i = threadIdx.x; i < 256; i += 32) {
        unsigned int v = w[i];
        if (v > 1u) i32 = false;
        if (v != 0u && v != 0x3F800000u) f32 = false;
    }
    i32 = __all_sync(0xffffffffu, i32);
    f32 = __all_sync(0xffffffffu, f32);
    if (threadIdx.x == 0) g_mask_mode = i32 ? 1 : (f32 ? 2 : 0);
}

// ---------------------------------------------------------------------------
// K1: per-query-row effective GEMM with packed f32x2 FMA.
// block b2: rows m in [b2*200, b2*200+200):
//   pre1[m,n] = qa[n] + sum_d facts[m,d]*wef[d,n]
// thread tile: 8 rows x 4 cols; row operand loads as packed f32x2 pairs.
// ---------------------------------------------------------------------------
__global__ __launch_bounds__(320) void k1_gemm1(
    const float* __restrict__ query, const float* __restrict__ facts,
    const float* __restrict__ W1, const float* __restrict__ b1v)
{
    extern __shared__ float sm[];
    float* q   = sm;                      // 128
    float* qa  = sm + 128;                // 80
    float* wef = sm + 208;                // 128*80
    float* fs  = sm + 208 + DD*NL1;       // 132*128 transposed facts chunk
    const int tid = threadIdx.x;
    const int b2  = blockIdx.x;

    if (tid < DD) q[tid] = query[b2*DD + tid];
    __syncthreads();

    for (int i = tid; i < DD*NL1; i += 320) {
        int d = i / NL1, n = i - d*NL1;
        wef[i] = W1[(DD+d)*NL1 + n] - W1[(3*DD+d)*NL1 + n] + q[d]*W1[(2*DD+d)*NL1 + n];
    }
    if (tid < NL1) {
        float s = b1v[tid];
        #pragma unroll 4
        for (int d = 0; d < DD; d++)
            s += q[d]*(W1[d*NL1 + tid] + W1[(3*DD+d)*NL1 + tid]);
        qa[tid] = s;
    }
    __syncthreads();

    const int tx   = tid & 7;          // 8 rows each
    const int half = (tid >> 3) & 1;   // +64 rows
    const int ty   = tid >> 4;         // 0..19, 4 cols each
    const int rowbase = half*64 + tx*8;
    const float4 qv = *reinterpret_cast<const float4*>(qa + (ty<<2));

    for (int mb = 0; mb < SQ; mb += 128) {
        const int rows = min(128, SQ - mb);
        const float* fp = facts + (size_t)(b2*SQ + mb)*DD;
        // load + transpose facts chunk (float4 loads, scalar transposed stores)
        for (int i = tid; i < 32*128; i += 320) {
            int r = i >> 5, d4 = (i & 31) << 2;
            float4 v = (r < rows) ? *reinterpret_cast<const float4*>(fp + (size_t)r*DD + d4)
                                  : make_float4(0.f,0.f,0.f,0.f);
            fs[(d4+0)*132 + r] = v.x;
            fs[(d4+1)*132 + r] = v.y;
            fs[(d4+2)*132 + r] = v.z;
            fs[(d4+3)*132 + r] = v.w;
        }
        __syncthreads();

        ull acc[4][4];
        #pragma unroll
        for (int p = 0; p < 4; p++)
            #pragma unroll
            for (int j = 0; j < 4; j++) acc[p][j] = 0ull;

        #pragma unroll 2
        for (int d = 0; d < DD; d++) {
            const ulonglong2 f01 = *reinterpret_cast<const ulonglong2*>(fs + d*132 + rowbase);
            const ulonglong2 f23 = *reinterpret_cast<const ulonglong2*>(fs + d*132 + rowbase + 4);
            const float4 wv = *reinterpret_cast<const float4*>(wef + d*NL1 + (ty<<2));
            ull wd0, wd1, wd2, wd3;
            DUPF2(wd0, wv.x); DUPF2(wd1, wv.y); DUPF2(wd2, wv.z); DUPF2(wd3, wv.w);
            FFMA2(acc[0][0], f01.x, wd0); FFMA2(acc[0][1], f01.x, wd1);
            FFMA2(acc[0][2], f01.x, wd2); FFMA2(acc[0][3], f01.x, wd3);
            FFMA2(acc[1][0], f01.y, wd0); FFMA2(acc[1][1], f01.y, wd1);
            FFMA2(acc[1][2], f01.y, wd2); FFMA2(acc[1][3], f01.y, wd3);
            FFMA2(acc[2][0], f23.x, wd0); FFMA2(acc[2][1], f23.x, wd1);
            FFMA2(acc[2][2], f23.x, wd2); FFMA2(acc[2][3], f23.x, wd3);
            FFMA2(acc[3][0], f23.y, wd0); FFMA2(acc[3][1], f23.y, wd1);
            FFMA2(acc[3][2], f23.y, wd2); FFMA2(acc[3][3], f23.y, wd3);
        }

        #pragma unroll
        for (int p = 0; p < 4; p++) {
            float lo0,hi0,lo1,hi1,lo2,hi2,lo3,hi3;
            UNPK2(lo0,hi0,acc[p][0]); UNPK2(lo1,hi1,acc[p][1]);
            UNPK2(lo2,hi2,acc[p][2]); UNPK2(lo3,hi3,acc[p][3]);
            int r0 = mb + rowbase + p*2;
            if (r0 < SQ) {
                float4 o = make_float4(lo0+qv.x, lo1+qv.y, lo2+qv.z, lo3+qv.w);
                *reinterpret_cast<float4*>(g_H1 + (size_t)(b2*SQ + r0)*NL1 + (ty<<2)) = o;
            }
            if (r0+1 < SQ) {
                float4 o = make_float4(hi0+qv.x, hi1+qv.y, hi2+qv.z, hi3+qv.w);
                *reinterpret_cast<float4*>(g_H1 + (size_t)(b2*SQ + r0+1)*NL1 + (ty<<2)) = o;
            }
        }
        __syncthreads();
    }
}

// ---------------------------------------------------------------------------
// K2: stats over S for layer 1, vectorized float4. element (s,b,l) at
// s*81920 + b*80 + l. thread handles 4 consecutive (b,l) keys.
// ---------------------------------------------------------------------------
__global__ void k2_stats1()
{
    int idx4 = blockIdx.x*blockDim.x + threadIdx.x;   // 0..20479
    if (idx4 >= (BB*NL1)/4) return;
    const float* base = g_H1 + idx4*4;
    float4 s1 = make_float4(0,0,0,0), s2 = make_float4(0,0,0,0);
    #pragma unroll 4
    for (int s = 0; s < SQ; s++) {
        float4 v = *reinterpret_cast<const float4*>(base + (size_t)s*BB*NL1);
        s1.x += v.x; s1.y += v.y; s1.z += v.z; s1.w += v.w;
        s2.x = fmaf(v.x,v.x,s2.x); s2.y = fmaf(v.y,v.y,s2.y);
        s2.z = fmaf(v.z,v.z,s2.z); s2.w = fmaf(v.w,v.w,s2.w);
    }
    const float inS = 1.0f/SQ, inV = 1.0f/(SQ-1);
    float4 mu = make_float4(s1.x*inS, s1.y*inS, s1.z*inS, s1.w*inS);
    float4 is;
    is.x = rsqrtf(fmaxf((s2.x - s1.x*mu.x)*inV, 1e-20f));
    is.y = rsqrtf(fmaxf((s2.y - s1.y*mu.y)*inV, 1e-20f));
    is.z = rsqrtf(fmaxf((s2.z - s1.z*mu.z)*inV, 1e-20f));
    is.w = rsqrtf(fmaxf((s2.w - s1.w*mu.w)*inV, 1e-20f));
    *reinterpret_cast<float4*>(g_mean1 + idx4*4) = mu;
    *reinterpret_cast<float4*>(g_istd1 + idx4*4) = is;
}

// ---------------------------------------------------------------------------
// K3: dice(H1) @ W2 + b2 -> H2. 128 rows/block. tanh.approx sigmoid,
// packed f32x2 GEMM (thread tile 4 rows x 4 cols).
// ---------------------------------------------------------------------------
__global__ __launch_bounds__(320) void k3_dice_gemm2(
    const float* __restrict__ W2, const float* __restrict__ b2v,
    const float* __restrict__ a1p)
{
    extern __shared__ float sm[];
    float* hs  = sm;               // 80 * 132
    float* w2s = sm + NL1*132;     // 80*40
    float* bs  = w2s + NL1*NL2;    // 40
    const int tid = threadIdx.x;
    const int m0  = blockIdx.x * 128;
    const float alpha = a1p[0];
    const float c0 = 0.5f*(1.0f + alpha);
    const float c1 = 0.5f*(1.0f - alpha);

    for (int i = tid; i < NL1*NL2; i += 320) w2s[i] = W2[i];
    if (tid < NL2) bs[tid] = b2v[tid];

    for (int i = tid; i < 128*NL1; i += 320) {
        int r = i / NL1, l = i - r*NL1;
        int m = m0 + r;
        float v = g_H1[(size_t)m0*NL1 + i];
        int b = m & (BB-1);
        float z = (v - g_mean1[b*NL1 + l]) * g_istd1[b*NL1 + l];
        float t;
        asm("tanh.approx.f32 %0, %1;" : "=f"(t) : "f"(0.5f*z));
        hs[l*132 + r] = v * fmaf(c1, t, c0);
    }
    __syncthreads();

    const int tx = tid & 31;   // 4 rows each -> 128
    const int ty = tid >> 5;   // 0..9, 4 cols each -> 40
    ull acc[2][4];
    #pragma unroll
    for (int p = 0; p < 2; p++)
        #pragma unroll
        for (int j = 0; j < 4; j++) acc[p][j] = 0ull;

    #pragma unroll 4
    for (int k = 0; k < NL1; k++) {
        const ulonglong2 fpr = *reinterpret_cast<const ulonglong2*>(hs + k*132 + (tx<<2));
        const float4 wv = *reinterpret_cast<const float4*>(w2s + k*NL2 + (ty<<2));
        ull wd0, wd1, wd2, wd3;
        DUPF2(wd0, wv.x); DUPF2(wd1, wv.y); DUPF2(wd2, wv.z); DUPF2(wd3, wv.w);
        FFMA2(acc[0][0], fpr.x, wd0); FFMA2(acc[0][1], fpr.x, wd1);
        FFMA2(acc[0][2], fpr.x, wd2); FFMA2(acc[0][3], fpr.x, wd3);
        FFMA2(acc[1][0], fpr.y, wd0); FFMA2(acc[1][1], fpr.y, wd1);
        FFMA2(acc[1][2], fpr.y, wd2); FFMA2(acc[1][3], fpr.y, wd3);
    }

    const float4 bv = *reinterpret_cast<const float4*>(bs + (ty<<2));
    #pragma unroll
    for (int p = 0; p < 2; p++) {
        float lo0,hi0,lo1,hi1,lo2,hi2,lo3,hi3;
        UNPK2(lo0,hi0,acc[p][0]); UNPK2(lo1,hi1,acc[p][1]);
        UNPK2(lo2,hi2,acc[p][2]); UNPK2(lo3,hi3,acc[p][3]);
        int m = m0 + (tx<<2) + p*2;
        float4 o0 = make_float4(lo0+bv.x, lo1+bv.y, lo2+bv.z, lo3+bv.w);
        float4 o1 = make_float4(hi0+bv.x, hi1+bv.y, hi2+bv.z, hi3+bv.w);
        *reinterpret_cast<float4*>(g_H2 + (size_t)m*NL2 + (ty<<2)) = o0;
        *reinterpret_cast<float4*>(g_H2 + (size_t)(m+1)*NL2 + (ty<<2)) = o1;
    }
}

// ---------------------------------------------------------------------------
// K456: per-batch-column fused stats2 + dice2 + W3 dot + masked softmax +
// output scaling. One block per b.
// ---------------------------------------------------------------------------
__global__ __launch_bounds__(256) void k456_fused(
    const void* __restrict__ mask, const float* __restrict__ facts,
    const float* __restrict__ W3, const float* __restrict__ b3,
    const float* __restrict__ a2p, float* __restrict__ out)
{
    __shared__ float hcol[SQ*NL2];   // 200*40
    __shared__ float mstat[NL2], istat[NL2], w3s[NL2];
    __shared__ float wgt[SQ];
    __shared__ float red[8];
    const int b = blockIdx.x, tid = threadIdx.x;
    const int lane = tid & 31, wrp = tid >> 5;
    const float MASK_FILL = -4294967295.0f;
    const int mode = g_mask_mode;
    const float alpha = a2p[0];

    if (tid < NL2) w3s[tid] = W3[tid];

    // load H2 column (float4)
    for (int i4 = tid; i4 < SQ*NL2/4; i4 += 256) {
        int s = i4 / 10, l4 = (i4 - s*10) << 2;
        *reinterpret_cast<float4*>(hcol + s*NL2 + l4) =
            *reinterpret_cast<const float4*>(g_H2 + (size_t)s*BB*NL2 + b*NL2 + l4);
    }
    __syncthreads();

    // stats over s: warp wrp owns l in [wrp*5, wrp*5+5)
    #pragma unroll
    for (int k = 0; k < 5; k++) {
        int l = wrp*5 + k;
        float s1 = 0.f, s2 = 0.f;
        for (int s = lane; s < SQ; s += 32) {
            float v = hcol[s*NL2 + l];
            s1 += v; s2 = fmaf(v, v, s2);
        }
        #pragma unroll
        for (int o = 16; o; o >>= 1) {
            s1 += __shfl_xor_sync(0xffffffffu, s1, o);
            s2 += __shfl_xor_sync(0xffffffffu, s2, o);
        }
        if (lane == 0) {
            float mu = s1 * (1.0f/SQ);
            mstat[l] = mu;
            istat[l] = rsqrtf(fmaxf((s2 - s1*mu)*(1.0f/(SQ-1)), 1e-20f));
        }
    }
    __syncthreads();

    // logits (exact expf sigmoid, layer 2)
    float my = -3.4028235e38f;
    if (tid < SQ) {
        float acc = 0.f;
        #pragma unroll
        for (int l = 0; l < NL2; l++) {
            float v = hcol[tid*NL2 + l];
            float z = (v - mstat[l]) * istat[l];
            float p = 1.0f/(1.0f + __expf(-z));
            acc = fmaf(v * (alpha + (1.0f-alpha)*p), w3s[l], acc);
        }
        float lg = acc + b3[0];
        int idx = tid*BB + b;
        bool mv;
        if (mode == 1)      mv = ((const int*)mask)[idx] != 0;
        else if (mode == 2) mv = ((const float*)mask)[idx] != 0.0f;
        else                mv = ((const unsigned char*)mask)[idx] != 0;
        my = mv ? lg : MASK_FILL;
    }
    // block max
    float v = my;
    #pragma unroll
    for (int o = 16; o; o >>= 1) v = fmaxf(v, __shfl_xor_sync(0xffffffffu, v, o));
    if (lane == 0) red[wrp] = v;
    __syncthreads();
    float mx = red[0];
    #pragma unroll
    for (int i = 1; i < 8; i++) mx = fmaxf(mx, red[i]);
    __syncthreads();

    float e = (tid < SQ) ? __expf(my - mx) : 0.0f;
    float sv = e;
    #pragma unroll
    for (int o = 16; o; o >>= 1) sv += __shfl_xor_sync(0xffffffffu, sv, o);
    if (lane == 0) red[wrp] = sv;
    __syncthreads();
    float tot = 0.0f;
    #pragma unroll
    for (int i = 0; i < 8; i++) tot += red[i];
    if (tid < SQ) wgt[tid] = e / tot;
    __syncthreads();

    // out = wgt[s] * facts, float4
    const float* fb = facts + b*DD;
    float*       ob = out   + b*DD;
    for (int i = tid; i < SQ*(DD/4); i += 256) {
        int s = i >> 5, d4 = (i & 31) << 2;
        size_t off = (size_t)s*BB*DD + d4;
        float4 fv = *reinterpret_cast<const float4*>(fb + off);
        float w = wgt[s];
        float4 o = make_float4(w*fv.x, w*fv.y, w*fv.z, w*fv.w);
        *reinterpret_cast<float4*>(ob + off) = o;
    }
}

// ---------------------------------------------------------------------------
extern "C" void kernel_launch(void* const* d_in, const int* in_sizes, int n_in,
                              void* d_out, int out_size)
{
    const float* query = (const float*)d_in[0];
    const float* facts = (const float*)d_in[1];
    const void*  mask  = d_in[2];
    const float* W1 = (const float*)d_in[3];
    const float* b1 = (const float*)d_in[4];
    const float* a1 = (const float*)d_in[5];
    const float* W2 = (const float*)d_in[6];
    const float* b2 = (const float*)d_in[7];
    const float* a2 = (const float*)d_in[8];
    const float* W3 = (const float*)d_in[9];
    const float* b3 = (const float*)d_in[10];
    float* out = (float*)d_out;

    const size_t sm1 = (size_t)(128 + NL1 + DD*NL1 + 132*128) * sizeof(float);  // ~109.4 KB
    const size_t sm3 = (size_t)(NL1*132 + NL1*NL2 + NL2) * sizeof(float);       // ~55.2 KB
    cudaFuncSetAttribute(k1_gemm1,      cudaFuncAttributeMaxDynamicSharedMemorySize, (int)sm1);
    cudaFuncSetAttribute(k3_dice_gemm2, cudaFuncAttributeMaxDynamicSharedMemorySize, (int)sm3);

    k0_detect_mask<<<1, 32>>>(mask);
    k1_gemm1<<<BB, 320, sm1>>>(query, facts, W1, b1);
    k2_stats1<<<80, 256>>>();
    k3_dice_gemm2<<<M_TOT/128, 320, sm3>>>(W2, b2, a1);
    k456_fused<<<BB, 256>>>(mask, facts, W3, b3, a2, out);
}